// round 7
// baseline (speedup 1.0000x reference)
#include <cuda_runtime.h>

// Problem constants
#define Bn 4
#define Ln 2048
#define Dn 256
#define SLOTS 64
#define ROWS 192          // SLOTS * 3
#define MPAD 260          // padded stride (words): bank-stride 4 -> conflict-free LDS.128
#define TILE 56           // 4 * 37 = 148 blocks = one full wave
#define CH 8              // positions per chunk
#define NT 512            // 16 warps: 6 producer (GEMM) + 10 consumer (argmax+gather)
#define TILES_PER_B 37

// G buffer: [2] x (gsm[8][192] + part[8][192]) = 2 x 3072 words
#define GBUF 3072
// smem layout (words)
#define OFF_G    (ROWS * MPAD)                // 49920
#define OFF_BIAS (OFF_G + 2 * GBUF)           // +6144
#define OFF_BEST (OFF_BIAS + ROWS)            // +192
#define SMEM_WORDS (OFF_BEST + CH * SLOTS)    // +512 -> 56768 words = 227072 B

// named barrier ids (0 reserved for __syncthreads)
#define BAR_FULL0 1
#define BAR_FULL1 2
#define BAR_EMPTY0 3
#define BAR_EMPTY1 4

typedef unsigned long long u64;

__device__ __forceinline__ void bar_sync(int id) {
    asm volatile("bar.sync %0, %1;" :: "r"(id), "r"(NT) : "memory");
}
__device__ __forceinline__ void bar_arrive(int id) {
    asm volatile("bar.arrive %0, %1;" :: "r"(id), "r"(NT) : "memory");
}

__device__ __forceinline__ u64 fma2(u64 a, u64 b, u64 c) {
    u64 d;
    asm("fma.rn.f32x2 %0, %1, %2, %3;" : "=l"(d) : "l"(a), "l"(b), "l"(c));
    return d;
}
__device__ __forceinline__ u64 add2(u64 a, u64 b) {
    u64 d;
    asm("add.rn.f32x2 %0, %1, %2;" : "=l"(d) : "l"(a), "l"(b));
    return d;
}
__device__ __forceinline__ float hsum2(u64 a) {
    float lo, hi;
    asm("mov.b64 {%0,%1}, %2;" : "=f"(lo), "=f"(hi) : "l"(a));
    return lo + hi;
}

// Producer GEMM slice: 2 columns (j0, j0+96), half-K (32 d4), 8 rows.
// x via warp-uniform broadcast LDG.128 from gmem (L1/L2 resident).
__device__ __forceinline__ void gemm_chunk(
    const float* __restrict__ xrow,            // &x[b][c0][0]
    const ulonglong2* __restrict__ mp0,
    const ulonglong2* __restrict__ mp1,
    float* __restrict__ gdst, int d4b, int j0)
{
    const ulonglong2* xp = (const ulonglong2*)xrow;
    u64 a0[8], a1[8];
    #pragma unroll
    for (int r = 0; r < 8; r++) { a0[r] = 0ULL; a1[r] = 0ULL; }
    #pragma unroll 4
    for (int d4 = d4b; d4 < d4b + 32; ++d4) {
        ulonglong2 m0 = mp0[d4];               // 4-phase LDS.128 (bank-perfect)
        ulonglong2 m1 = mp1[d4];
        #pragma unroll
        for (int r = 0; r < 8; r++) {
            ulonglong2 xv = xp[r * 64 + d4];   // broadcast LDG.128, stride 64 = 256 floats
            a0[r] = fma2(m0.x, xv.x, a0[r]);
            a0[r] = fma2(m0.y, xv.y, a0[r]);
            a1[r] = fma2(m1.x, xv.x, a1[r]);
            a1[r] = fma2(m1.y, xv.y, a1[r]);
        }
    }
    #pragma unroll
    for (int r = 0; r < 8; r++) {
        gdst[r * ROWS + j0]      = hsum2(a0[r]);
        gdst[r * ROWS + j0 + 96] = hsum2(a1[r]);
    }
}

__device__ __forceinline__ void gather_one(
    const float* __restrict__ mem_s, const int* __restrict__ best_s,
    float* __restrict__ out, size_t orow, int it)
{
    int p = it >> 6, d4 = it & 63;
    const int4* bp = (const int4*)(best_s + p * SLOTS);
    u64 ax[4] = {0ULL, 0ULL, 0ULL, 0ULL};
    u64 ay[4] = {0ULL, 0ULL, 0ULL, 0ULL};
    #pragma unroll
    for (int m4 = 0; m4 < 16; m4++) {
        int4 r4 = bp[m4];                      // warp-uniform broadcast
        int q = m4 & 3;
        ulonglong2 v;
        v = ((const ulonglong2*)(mem_s + r4.x))[d4];
        ax[q] = add2(ax[q], v.x); ay[q] = add2(ay[q], v.y);
        v = ((const ulonglong2*)(mem_s + r4.y))[d4];
        ax[q] = add2(ax[q], v.x); ay[q] = add2(ay[q], v.y);
        v = ((const ulonglong2*)(mem_s + r4.z))[d4];
        ax[q] = add2(ax[q], v.x); ay[q] = add2(ay[q], v.y);
        v = ((const ulonglong2*)(mem_s + r4.w))[d4];
        ax[q] = add2(ax[q], v.x); ay[q] = add2(ay[q], v.y);
    }
    u64 s0 = add2(add2(ax[0], ax[1]), add2(ax[2], ax[3]));
    u64 s1 = add2(add2(ay[0], ay[1]), add2(ay[2], ay[3]));
    float x0, x1, y0, y1;
    asm("mov.b64 {%0,%1}, %2;" : "=f"(x0), "=f"(x1) : "l"(s0));
    asm("mov.b64 {%0,%1}, %2;" : "=f"(y0), "=f"(y1) : "l"(s1));
    ((float4*)(out + (orow + p) * Dn))[d4] = make_float4(x0, x1, y0, y1);
}

__global__ void __launch_bounds__(NT, 1)
pnm_kernel(const float* __restrict__ x,
           const float* __restrict__ mem,
           const float* __restrict__ bias,
           float* __restrict__ out)
{
    extern __shared__ float smem[];
    float* mem_s  = smem;                     // [ROWS][MPAD]
    float* gbuf   = smem + OFF_G;             // [2][2][8][192]  (buf, kc-half, row, col)
    float* bias_s = smem + OFF_BIAS;          // [192]
    int*   best_s = (int*)(smem + OFF_BEST);  // [8][64]

    const int tid  = threadIdx.x;
    const int b    = blockIdx.x / TILES_PER_B;
    const int l0   = (blockIdx.x % TILES_PER_B) * TILE;
    const int lend = (l0 + TILE < Ln) ? (l0 + TILE) : Ln;
    const int nc   = (lend - l0) / CH;        // 7 or 4

    const float* xb = x + (size_t)b * Ln * Dn;
    const size_t orow0 = (size_t)b * Ln;

    // ---- stage memory + bias ----
    for (int i = tid; i < ROWS * (Dn / 4); i += NT) {
        int r = i >> 6, c = i & 63;
        ((float4*)(mem_s + r * MPAD))[c] = ((const float4*)mem)[i];
    }
    if (tid < ROWS) bias_s[tid] = bias[tid];
    __syncthreads();   // mem_s needed by seed computation below

    // ---- prologue: seed buffer 1, rows 6,7 with G(l0-2), G(l0-1) ----
    // gsm-half gets the full-K value; part-half gets 0 (argmax sums the halves).
    if (tid < 2 * ROWS) {
        int rI = tid / ROWS, jj = tid % ROWS;
        int lp = l0 - 2 + rI;
        float v = 0.f;
        if (lp >= 0) {
            const ulonglong2* mpr = (const ulonglong2*)(mem_s + jj * MPAD);
            const ulonglong2* xp  = (const ulonglong2*)(xb + (size_t)lp * Dn);
            u64 p0 = 0ULL, p1 = 0ULL;
            #pragma unroll 8
            for (int d4 = 0; d4 < 64; ++d4) {
                ulonglong2 m  = mpr[d4];
                ulonglong2 xv = xp[d4];
                p0 = fma2(m.x, xv.x, p0);
                p1 = fma2(m.y, xv.y, p1);
            }
            v = hsum2(add2(p0, p1));
        }
        gbuf[GBUF + (6 + rI) * ROWS + jj] = v;                    // gsm half
        gbuf[GBUF + CH * ROWS + (6 + rI) * ROWS + jj] = 0.f;      // part half
    }
    __syncthreads();

    if (tid < 192) {
        // ================= PRODUCER (6 warps): GEMM chunks =================
        const int q  = tid % 96;              // col pair: j0=q, j1=q+96
        const int kc = tid / 96;              // 0/1, warp-uniform
        const ulonglong2* mp0 = (const ulonglong2*)(mem_s + q * MPAD);
        const ulonglong2* mp1 = (const ulonglong2*)(mem_s + (q + 96) * MPAD);
        const int d4b = kc * 32;
        const int goff = kc * (CH * ROWS);    // gsm half vs part half

        for (int ci = 0; ci < nc; ci++) {
            if (ci > 0) bar_sync(BAR_EMPTY0 + (ci & 1));   // argmax_{ci-1} done
            float* gdst = gbuf + (ci & 1) * GBUF + goff;
            gemm_chunk(xb + (size_t)(l0 + ci * CH) * Dn, mp0, mp1, gdst, d4b, q);
            bar_arrive(BAR_FULL0 + (ci & 1));
        }
    } else {
        // ================ CONSUMER (10 warps): argmax + gather ================
        const int t = tid - 192;              // 0..319

        for (int ci = 0; ci < nc; ci++) {
            bar_sync(BAR_FULL0 + (ci & 1));   // G_ci ready (also orders vs gather_{ci-1})

            const float* cur = gbuf + (ci & 1) * GBUF;
            const float* prv = gbuf + ((ci & 1) ^ 1) * GBUF;

            // argmax: 512 items over 320 threads
            #pragma unroll
            for (int ii = 0; ii < 2; ii++) {
                int item = (ii == 0) ? t : (t + 320);
                if (ii == 1 && t >= 192) break;
                int p  = item >> 6;
                int m3 = (item & 63) * 3;
                float sc[3];
                #pragma unroll
                for (int n = 0; n < 3; n++) {
                    int r   = p + n - 2;
                    int idx = m3 + n;
                    float s;
                    if (r < 0) {
                        int o = (8 + r) * ROWS + idx;
                        s = prv[o] + prv[CH * ROWS + o];
                    } else {
                        int o = r * ROWS + idx;
                        s = cur[o] + cur[CH * ROWS + o];
                    }
                    sc[n] = s + bias_s[idx];
                }
                int   bn = 0;
                float bv = sc[0];
                if (sc[1] > bv) { bv = sc[1]; bn = 1; }
                if (sc[2] > bv) { bv = sc[2]; bn = 2; }
                best_s[item] = (m3 + bn) * MPAD;
            }

            if (ci + 1 < nc) bar_arrive(BAR_EMPTY0 + ((ci + 1) & 1));

            // gather: 512 items over 320 threads (reads best_s + mem_s only)
            gather_one(mem_s, best_s, out, orow0 + l0 + ci * CH, t);
            if (t < 192)
                gather_one(mem_s, best_s, out, orow0 + l0 + ci * CH, t + 320);
        }
    }
}

extern "C" void kernel_launch(void* const* d_in, const int* in_sizes, int n_in,
                              void* d_out, int out_size)
{
    const float* x    = (const float*)d_in[0];   // (4, 2048, 256) f32
    const float* mem  = (const float*)d_in[1];   // (64, 3, 256)   f32
    const float* bias = (const float*)d_in[2];   // (64, 3)        f32
    float* out        = (float*)d_out;           // (4, 2048, 256) f32

    (void)in_sizes; (void)n_in; (void)out_size;

    const int smem_bytes = SMEM_WORDS * (int)sizeof(float);   // 227072
    cudaFuncSetAttribute(pnm_kernel,
                         cudaFuncAttributeMaxDynamicSharedMemorySize,
                         smem_bytes);

    pnm_kernel<<<Bn * TILES_PER_B, NT, smem_bytes>>>(x, mem, bias, out);
}

// round 8
// speedup vs baseline: 1.0696x; 1.0696x over previous
#include <cuda_runtime.h>

// Problem constants
#define Bn 4
#define Ln 2048
#define Dn 256
#define SLOTS 64
#define ROWS 192          // SLOTS * 3
#define MPAD 260          // padded stride (words): bank-stride 4 -> conflict-free LDS.128
#define TILE 56           // 4 * 37 = 148 blocks = one full wave
#define CH 8              // positions per chunk
#define NT1 512           // K1 threads
#define NT2 1024          // K2 threads (32 warps, pure gather)
#define TILES_PER_B 37

// K1 smem layout (words)
#define OFF_GSM  (ROWS * MPAD)                // 49920 : gsm[8][192]  K-half 0
#define OFF_PART (OFF_GSM + CH * ROWS)        // +1536 : part[8][192] K-half 1
#define OFF_HEAD (OFF_PART + CH * ROWS)       // +1536 : head[2][2][192]
#define OFF_BIAS (OFF_HEAD + 2 * 2 * ROWS)    // +768
#define OFF_XS   (OFF_BIAS + ROWS)            // +192  : xs[8][256]
#define SMEM1_WORDS (OFF_XS + CH * Dn)        // +2048 -> 55952 words = 223808 B

#define SMEM2_WORDS (ROWS * MPAD)             // K2: mem_s only = 199680 B

// inter-kernel scratch: premultiplied best row offsets, [B*L][SLOTS]
__device__ int g_best[Bn * Ln * SLOTS];       // 2 MB

typedef unsigned long long u64;

__device__ __forceinline__ u64 fma2(u64 a, u64 b, u64 c) {
    u64 d;
    asm("fma.rn.f32x2 %0, %1, %2, %3;" : "=l"(d) : "l"(a), "l"(b), "l"(c));
    return d;
}
__device__ __forceinline__ u64 add2(u64 a, u64 b) {
    u64 d;
    asm("add.rn.f32x2 %0, %1, %2;" : "=l"(d) : "l"(a), "l"(b));
    return d;
}
__device__ __forceinline__ float hsum2(u64 a) {
    float lo, hi;
    asm("mov.b64 {%0,%1}, %2;" : "=f"(lo), "=f"(hi) : "l"(a));
    return lo + hi;
}

// GEMM slice: 2 columns (j0, j0+96), half-K (32 d4), 8 rows. x via broadcast LDS.
__device__ __forceinline__ void gemm_chunk(
    const float* __restrict__ xs,
    const ulonglong2* __restrict__ mp0,
    const ulonglong2* __restrict__ mp1,
    float* __restrict__ gdst, int d4b, int j0)
{
    const ulonglong2* xp = (const ulonglong2*)xs;
    u64 a0[8], a1[8];
    #pragma unroll
    for (int r = 0; r < 8; r++) { a0[r] = 0ULL; a1[r] = 0ULL; }
    #pragma unroll 4
    for (int d4 = d4b; d4 < d4b + 32; ++d4) {
        ulonglong2 m0 = mp0[d4];               // 4-phase LDS.128 (bank-perfect)
        ulonglong2 m1 = mp1[d4];
        #pragma unroll
        for (int r = 0; r < 8; r++) {
            ulonglong2 xv = xp[r * 64 + d4];   // warp-uniform broadcast LDS.128
            a0[r] = fma2(m0.x, xv.x, a0[r]);
            a0[r] = fma2(m0.y, xv.y, a0[r]);
            a1[r] = fma2(m1.x, xv.x, a1[r]);
            a1[r] = fma2(m1.y, xv.y, a1[r]);
        }
    }
    #pragma unroll
    for (int r = 0; r < 8; r++) {
        gdst[r * ROWS + j0]      = hsum2(a0[r]);
        gdst[r * ROWS + j0 + 96] = hsum2(a1[r]);
    }
}

// ======================= Kernel 1: scores + argmax =======================
__global__ void __launch_bounds__(NT1, 1)
pnm_scores_kernel(const float* __restrict__ x,
                  const float* __restrict__ mem,
                  const float* __restrict__ bias)
{
    extern __shared__ float smem[];
    float* mem_s  = smem;                     // [ROWS][MPAD]
    float* gsm    = smem + OFF_GSM;           // [8][192]
    float* part   = smem + OFF_PART;          // [8][192]
    float* head   = smem + OFF_HEAD;          // [2][2][192]
    float* bias_s = smem + OFF_BIAS;          // [192]
    float* xs     = smem + OFF_XS;            // [8][256]

    const int tid  = threadIdx.x;
    const int b    = blockIdx.x / TILES_PER_B;
    const int l0   = (blockIdx.x % TILES_PER_B) * TILE;
    const int lend = (l0 + TILE < Ln) ? (l0 + TILE) : Ln;
    const int nc   = (lend - l0) / CH;        // 7 or 4

    const float* xb = x + (size_t)b * Ln * Dn;

    // ---- stage memory + bias + x chunk 0 ----
    for (int i = tid; i < ROWS * (Dn / 4); i += NT1) {
        int r = i >> 6, c = i & 63;
        ((float4*)(mem_s + r * MPAD))[c] = ((const float4*)mem)[i];
    }
    if (tid < ROWS) bias_s[tid] = bias[tid];
    for (int i = tid; i < CH * (Dn / 4); i += NT1) {
        int r = i >> 6, c = i & 63;
        ((float4*)(xs + r * Dn))[c] =
            ((const float4*)(xb + (size_t)(l0 + r) * Dn))[c];
    }
    __syncthreads();

    // GEMM: 192 threads (6 warps) = 96 col-pairs x 2 K-halves (kc warp-uniform)
    const bool is_gemm = (tid < 192);
    const int  q  = tid % 96;                 // col pair: j0=q, j1=q+96
    const int  kc = (tid / 96) & 1;
    const ulonglong2* mp0 = (const ulonglong2*)(mem_s + q * MPAD);
    const ulonglong2* mp1 = (const ulonglong2*)(mem_s + (q + 96) * MPAD);
    float* gdst = (kc == 0) ? gsm : part;
    const int d4b = kc * 32;

    // head-roll mapping (first 384 threads)
    const int rI = tid / ROWS;                // 0/1 for tid<384
    const int jj = tid % ROWS;

    // ---- prologue: head[0] (l' = l0-2, l0-1, full-K) + GEMM chunk 0 ----
    if (tid < 2 * ROWS) {
        int lp = l0 - 2 + rI;
        float v = 0.f;
        if (lp >= 0) {
            const ulonglong2* mpr = (const ulonglong2*)(mem_s + jj * MPAD);
            const ulonglong2* xp  = (const ulonglong2*)(xb + (size_t)lp * Dn);
            u64 p0 = 0ULL, p1 = 0ULL;
            #pragma unroll 8
            for (int d4 = 0; d4 < 64; ++d4) {
                ulonglong2 m  = mpr[d4];
                ulonglong2 xv = xp[d4];
                p0 = fma2(m.x, xv.x, p0);
                p1 = fma2(m.y, xv.y, p1);
            }
            v = hsum2(add2(p0, p1));
        }
        head[rI * ROWS + jj] = v;             // buffer 0
    }
    if (is_gemm) gemm_chunk(xs, mp0, mp1, gdst, d4b, q);
    __syncthreads();

    for (int ci = 0; ci < nc; ci++) {
        const int c0  = l0 + ci * CH;
        const int cur = ci & 1;
        float* hc = head + cur * (2 * ROWS);
        float* hn = head + (cur ^ 1) * (2 * ROWS);

        // ===== Phase A: stage xs_{i+1} + roll + argmax -> g_best =====
        if (ci + 1 < nc) {
            for (int i = tid; i < CH * (Dn / 4); i += NT1) {
                int r = i >> 6, c = i & 63;
                ((float4*)(xs + r * Dn))[c] =
                    ((const float4*)(xb + (size_t)(c0 + CH + r) * Dn))[c];
            }
        }
        if (tid < 2 * ROWS) {   // roll: head_next[rI] = G row (6+rI) = l' = c0+6+rI
            int row = (6 + rI) * ROWS + jj;
            hn[rI * ROWS + jj] = gsm[row] + part[row];
        }
        {   // argmax: one (p, m) per thread (NT1 == CH*SLOTS)
            int p  = tid >> 6;
            int m3 = (tid & 63) * 3;
            float sc[3];
            #pragma unroll
            for (int n = 0; n < 3; n++) {
                int row = p + n - 2;
                int idx = m3 + n;
                float s;
                if (row < 0) {
                    s = hc[(row + 2) * ROWS + idx];
                } else {
                    int o = row * ROWS + idx;
                    s = gsm[o] + part[o];
                }
                sc[n] = s + bias_s[idx];
            }
            int   bn = 0;
            float bv = sc[0];
            if (sc[1] > bv) { bv = sc[1]; bn = 1; }
            if (sc[2] > bv) { bv = sc[2]; bn = 2; }
            // coalesced: consecutive tid -> consecutive address
            g_best[((size_t)b * Ln + c0 + p) * SLOTS + (tid & 63)] = (m3 + bn) * MPAD;
        }
        __syncthreads();

        // ===== Phase B: GEMM_{i+1} =====
        if (is_gemm && ci + 1 < nc)
            gemm_chunk(xs, mp0, mp1, gdst, d4b, q);
        __syncthreads();
    }
}

// ========================= Kernel 2: gather-sum =========================
__global__ void __launch_bounds__(NT2, 1)
pnm_gather_kernel(const float* __restrict__ mem,
                  float* __restrict__ out)
{
    extern __shared__ float smem[];
    float* mem_s = smem;                      // [ROWS][MPAD]

    const int tid  = threadIdx.x;
    const int b    = blockIdx.x / TILES_PER_B;
    const int l0   = (blockIdx.x % TILES_PER_B) * TILE;
    const int lend = (l0 + TILE < Ln) ? (l0 + TILE) : Ln;
    const int npos = lend - l0;

    // ---- stage memory ----
    for (int i = tid; i < ROWS * (Dn / 4); i += NT2) {
        int r = i >> 6, c = i & 63;
        ((float4*)(mem_s + r * MPAD))[c] = ((const float4*)mem)[i];
    }
    __syncthreads();

    const int*  bestg = g_best + ((size_t)b * Ln + l0) * SLOTS;
    float*      outg  = out + ((size_t)b * Ln + l0) * Dn;

    // items: npos * 64 (p, d4-group); warp spans one p, consecutive d4
    for (int it = tid; it < npos * (Dn / 4); it += NT2) {
        int p = it >> 6, d4 = it & 63;
        const int4* bp = (const int4*)(bestg + p * SLOTS);  // warp-uniform LDG
        u64 ax[4] = {0ULL, 0ULL, 0ULL, 0ULL};
        u64 ay[4] = {0ULL, 0ULL, 0ULL, 0ULL};
        #pragma unroll
        for (int m4 = 0; m4 < 16; m4++) {
            int4 r4 = bp[m4];
            int qq = m4 & 3;
            ulonglong2 v;
            v = ((const ulonglong2*)(mem_s + r4.x))[d4];
            ax[qq] = add2(ax[qq], v.x); ay[qq] = add2(ay[qq], v.y);
            v = ((const ulonglong2*)(mem_s + r4.y))[d4];
            ax[qq] = add2(ax[qq], v.x); ay[qq] = add2(ay[qq], v.y);
            v = ((const ulonglong2*)(mem_s + r4.z))[d4];
            ax[qq] = add2(ax[qq], v.x); ay[qq] = add2(ay[qq], v.y);
            v = ((const ulonglong2*)(mem_s + r4.w))[d4];
            ax[qq] = add2(ax[qq], v.x); ay[qq] = add2(ay[qq], v.y);
        }
        u64 s0 = add2(add2(ax[0], ax[1]), add2(ax[2], ax[3]));
        u64 s1 = add2(add2(ay[0], ay[1]), add2(ay[2], ay[3]));
        float x0, x1, y0, y1;
        asm("mov.b64 {%0,%1}, %2;" : "=f"(x0), "=f"(x1) : "l"(s0));
        asm("mov.b64 {%0,%1}, %2;" : "=f"(y0), "=f"(y1) : "l"(s1));
        ((float4*)(outg + (size_t)p * Dn))[d4] = make_float4(x0, x1, y0, y1);
    }
}

extern "C" void kernel_launch(void* const* d_in, const int* in_sizes, int n_in,
                              void* d_out, int out_size)
{
    const float* x    = (const float*)d_in[0];   // (4, 2048, 256) f32
    const float* mem  = (const float*)d_in[1];   // (64, 3, 256)   f32
    const float* bias = (const float*)d_in[2];   // (64, 3)        f32
    float* out        = (float*)d_out;           // (4, 2048, 256) f32

    (void)in_sizes; (void)n_in; (void)out_size;

    const int smem1 = SMEM1_WORDS * (int)sizeof(float);   // 223808
    const int smem2 = SMEM2_WORDS * (int)sizeof(float);   // 199680
    cudaFuncSetAttribute(pnm_scores_kernel,
                         cudaFuncAttributeMaxDynamicSharedMemorySize, smem1);
    cudaFuncSetAttribute(pnm_gather_kernel,
                         cudaFuncAttributeMaxDynamicSharedMemorySize, smem2);

    pnm_scores_kernel<<<Bn * TILES_PER_B, NT1, smem1>>>(x, mem, bias);
    pnm_gather_kernel<<<Bn * TILES_PER_B, NT2, smem2>>>(mem, out);
}